// round 1
// baseline (speedup 1.0000x reference)
#include <cuda_runtime.h>
#include <cuda_bf16.h>
#include <math.h>

// Problem constants
#define BB 2
#define SS 4096
#define DD 1024
#define HH 16
#define HDIM 64
#define MM 512
#define LL 1024          // 2*MM
#define HID 2816
#define NSTEP 8          // SS/MM

// ---------------- scratch (device globals; no allocation allowed) ----------------
__device__ float g_Y  [BB * SS * DD];   // attention outputs / om chain (32MB)
__device__ float g_Q  [BB * LL * DD];   // q buffer (only rows M..L used)
__device__ float g_K  [BB * LL * DD];
__device__ float g_V  [BB * LL * DD];
__device__ float g_OM2[BB * MM * DD];
__device__ float g_HN [BB * MM * DD];
__device__ float g_H1 [BB * MM * HID];
__device__ float g_H3 [BB * MM * HID];
__device__ float g_OMN[BB * MM * DD];

// ---------------- SGEMM: C[row,col] (+)= sum_k A[row,k]*B[k,col] ----------------
// Row mapping (for batched slices without copies):
//   A index = (r / Mchunk)*a_bs + ((r % Mchunk) + a_off)*K
//   C index = (r / Mchunk)*c_bs + ((r % Mchunk) + c_off)*N
// Requires: Mtot,N multiples of 64; K multiple of 16; Mchunk multiple of 64.
__global__ __launch_bounds__(256) void sgemm_kernel(
    const float* __restrict__ A, const float* __restrict__ B, float* __restrict__ C,
    int Mtot, int N, int K,
    long long a_bs, int a_off, int Mchunk,
    long long c_bs, int c_off, int acc)
{
    __shared__ float As[16][64];
    __shared__ float Bs[16][64];
    int tid = threadIdx.x;
    int tx = tid & 15, ty = tid >> 4;
    int block_m = blockIdx.y * 64;
    int block_n = blockIdx.x * 64;

    int la_r = tid >> 2;              // 0..63  (row in tile)
    int la_k = (tid & 3) << 2;        // 0,4,8,12
    int ga_row = block_m + la_r;
    const float* a_row_ptr = A + (long long)(ga_row / Mchunk) * a_bs
                               + (long long)((ga_row % Mchunk) + a_off) * K;

    int lb_r = tid >> 4;              // 0..15 (k in tile)
    int lb_c = (tid & 15) << 2;       // col
    const float* b_ptr = B + (long long)lb_r * N + block_n + lb_c;

    float accv[4][4];
    #pragma unroll
    for (int i = 0; i < 4; i++)
        #pragma unroll
        for (int j = 0; j < 4; j++) accv[i][j] = 0.f;

    for (int k0 = 0; k0 < K; k0 += 16) {
        float4 av = *(const float4*)(a_row_ptr + k0 + la_k);
        As[la_k + 0][la_r] = av.x;
        As[la_k + 1][la_r] = av.y;
        As[la_k + 2][la_r] = av.z;
        As[la_k + 3][la_r] = av.w;
        float4 bv = *(const float4*)(b_ptr + (long long)k0 * N);
        *(float4*)&Bs[lb_r][lb_c] = bv;
        __syncthreads();
        #pragma unroll
        for (int k = 0; k < 16; k++) {
            float4 a4 = *(const float4*)&As[k][ty << 2];
            float4 b4 = *(const float4*)&Bs[k][tx << 2];
            float ar[4] = {a4.x, a4.y, a4.z, a4.w};
            float br[4] = {b4.x, b4.y, b4.z, b4.w};
            #pragma unroll
            for (int i = 0; i < 4; i++)
                #pragma unroll
                for (int j = 0; j < 4; j++)
                    accv[i][j] += ar[i] * br[j];
        }
        __syncthreads();
    }

    #pragma unroll
    for (int i = 0; i < 4; i++) {
        int gr = block_m + (ty << 2) + i;
        float* c_row = C + (long long)(gr / Mchunk) * c_bs
                         + (long long)((gr % Mchunk) + c_off) * N + block_n + (tx << 2);
        if (acc) {
            float4 old = *(float4*)c_row;
            old.x += accv[i][0]; old.y += accv[i][1];
            old.z += accv[i][2]; old.w += accv[i][3];
            *(float4*)c_row = old;
        } else {
            float4 v = {accv[i][0], accv[i][1], accv[i][2], accv[i][3]};
            *(float4*)c_row = v;
        }
    }
}

// ---------------- RMSNorm: one block per row, D=1024 ----------------
__global__ __launch_bounds__(256) void rmsnorm_kernel(
    const float* __restrict__ X, const float* __restrict__ W, float* __restrict__ O)
{
    int row = blockIdx.x;
    int t = threadIdx.x;
    const float4* x = (const float4*)(X + (long long)row * DD);
    float4 xv = x[t];
    float ss = xv.x*xv.x + xv.y*xv.y + xv.z*xv.z + xv.w*xv.w;
    #pragma unroll
    for (int off = 16; off >= 1; off >>= 1)
        ss += __shfl_xor_sync(0xffffffffu, ss, off);
    __shared__ float red[8];
    if ((t & 31) == 0) red[t >> 5] = ss;
    __syncthreads();
    __shared__ float s_inv;
    if (t == 0) {
        float tot = 0.f;
        #pragma unroll
        for (int i = 0; i < 8; i++) tot += red[i];
        s_inv = rsqrtf(tot * (1.0f / DD) + 1e-5f);
    }
    __syncthreads();
    float inv = s_inv;
    float4 wv = ((const float4*)W)[t];
    float4 ov = {xv.x*inv*wv.x, xv.y*inv*wv.y, xv.z*inv*wv.z, xv.w*inv*wv.w};
    ((float4*)(O + (long long)row * DD))[t] = ov;
}

// ---------------- SwiGLU: h1 = silu(h1) * h3 (in place), float4 ----------------
__global__ void silu_mul_kernel(float* __restrict__ h1, const float* __restrict__ h3, int n4)
{
    int i = blockIdx.x * blockDim.x + threadIdx.x;
    if (i >= n4) return;
    float4 a = ((float4*)h1)[i];
    float4 b = ((const float4*)h3)[i];
    a.x = a.x / (1.f + expf(-a.x)) * b.x;
    a.y = a.y / (1.f + expf(-a.y)) * b.y;
    a.z = a.z / (1.f + expf(-a.z)) * b.z;
    a.w = a.w / (1.f + expf(-a.w)) * b.w;
    ((float4*)h1)[i] = a;
}

// ---------------- RoPE (in place) on rows [l_begin, l_begin+l_count) ----------------
__global__ void rope_kernel(float* __restrict__ T, const float* __restrict__ fcos,
                            const float* __restrict__ fsin, int l_begin, int l_count)
{
    int idx = blockIdx.x * blockDim.x + threadIdx.x;
    int total = BB * l_count * HH * (HDIM / 2);
    if (idx >= total) return;
    int i = idx & 31;
    int h = (idx >> 5) & 15;
    int rest = idx >> 9;
    int lr = rest % l_count;
    int b = rest / l_count;
    int l = l_begin + lr;
    float* p = T + ((long long)b * LL + l) * DD + h * HDIM + 2 * i;
    float c = fcos[l * 32 + i];
    float s = fsin[l * 32 + i];
    float2 v = *(float2*)p;
    float2 o = {v.x * c - v.y * s, v.x * s + v.y * c};
    *(float2*)p = o;
}

// ---------------- Flash attention (fp32), q rows M..L only ----------------
// grid: (qt=8, h=16, b=2), 256 threads, 64x64 tiles, online softmax.
// KP smem holds K tile transposed (d-major) for QK^T, then reused as P tile for PV.
__global__ __launch_bounds__(256) void attn_kernel(
    const float* __restrict__ Qg, const float* __restrict__ Kg, const float* __restrict__ Vg,
    float* __restrict__ Yg, int step)
{
    __shared__ float Qs[64][64];
    __shared__ float KP[64][64];
    __shared__ float Vs[64][64];
    int qt = blockIdx.x, h = blockIdx.y, b = blockIdx.z;
    int tid = threadIdx.x, tx = tid & 15, ty = tid >> 4;
    int r4 = ty << 2, c4 = tx << 2;

    const float* qbase = Qg + ((long long)b * LL + MM + qt * 64) * DD + h * HDIM;
    #pragma unroll
    for (int i = 0; i < 4; i++) {
        int r = (tid >> 4) + i * 16;
        int c = (tid & 15) << 2;
        *(float4*)&Qs[r][c] = *(const float4*)(qbase + (long long)r * DD + c);
    }

    float m_i[4], l_i[4], o[4][4];
    #pragma unroll
    for (int i = 0; i < 4; i++) {
        m_i[i] = -1e30f; l_i[i] = 0.f;
        #pragma unroll
        for (int j = 0; j < 4; j++) o[i][j] = 0.f;
    }

    int nkt = 9 + qt;   // key tiles: 0..8+qt, only the last is diagonal
    for (int kt = 0; kt < nkt; kt++) {
        __syncthreads();   // protects Qs first use + KP/Vs reuse
        const float* kbase = Kg + ((long long)b * LL + kt * 64) * DD + h * HDIM;
        const float* vbase = Vg + ((long long)b * LL + kt * 64) * DD + h * HDIM;
        #pragma unroll
        for (int i = 0; i < 4; i++) {
            int c  = tid >> 2;
            int d0 = ((tid & 3) << 2) + i * 16;
            float4 kv = *(const float4*)(kbase + (long long)c * DD + d0);
            KP[d0 + 0][c] = kv.x; KP[d0 + 1][c] = kv.y;
            KP[d0 + 2][c] = kv.z; KP[d0 + 3][c] = kv.w;
            int r = (tid >> 4) + i * 16;
            int cc = (tid & 15) << 2;
            *(float4*)&Vs[r][cc] = *(const float4*)(vbase + (long long)r * DD + cc);
        }
        __syncthreads();

        // S = Q K^T
        float s[4][4];
        #pragma unroll
        for (int i = 0; i < 4; i++)
            #pragma unroll
            for (int j = 0; j < 4; j++) s[i][j] = 0.f;
        #pragma unroll
        for (int d0 = 0; d0 < 64; d0 += 4) {
            float areg[4][4];
            #pragma unroll
            for (int i = 0; i < 4; i++) {
                float4 t = *(const float4*)&Qs[r4 + i][d0];
                areg[i][0] = t.x; areg[i][1] = t.y; areg[i][2] = t.z; areg[i][3] = t.w;
            }
            #pragma unroll
            for (int dd = 0; dd < 4; dd++) {
                float4 bt = *(const float4*)&KP[d0 + dd][c4];
                float br[4] = {bt.x, bt.y, bt.z, bt.w};
                #pragma unroll
                for (int i = 0; i < 4; i++)
                    #pragma unroll
                    for (int j = 0; j < 4; j++)
                        s[i][j] += areg[i][dd] * br[j];
            }
        }

        bool diag = (kt == 8 + qt);
        #pragma unroll
        for (int i = 0; i < 4; i++) {
            #pragma unroll
            for (int j = 0; j < 4; j++) {
                s[i][j] *= 0.125f;
                if (diag && (c4 + j > r4 + i)) s[i][j] = -1e30f;
            }
        }

        // online softmax update
        #pragma unroll
        for (int i = 0; i < 4; i++) {
            float tm = fmaxf(fmaxf(s[i][0], s[i][1]), fmaxf(s[i][2], s[i][3]));
            tm = fmaxf(tm, __shfl_xor_sync(0xffffffffu, tm, 8));
            tm = fmaxf(tm, __shfl_xor_sync(0xffffffffu, tm, 4));
            tm = fmaxf(tm, __shfl_xor_sync(0xffffffffu, tm, 2));
            tm = fmaxf(tm, __shfl_xor_sync(0xffffffffu, tm, 1));
            float mnew = fmaxf(m_i[i], tm);
            float alpha = expf(m_i[i] - mnew);
            float rs = 0.f;
            #pragma unroll
            for (int j = 0; j < 4; j++) {
                float p = expf(s[i][j] - mnew);
                s[i][j] = p; rs += p;
            }
            rs += __shfl_xor_sync(0xffffffffu, rs, 8);
            rs += __shfl_xor_sync(0xffffffffu, rs, 4);
            rs += __shfl_xor_sync(0xffffffffu, rs, 2);
            rs += __shfl_xor_sync(0xffffffffu, rs, 1);
            l_i[i] = l_i[i] * alpha + rs;
            m_i[i] = mnew;
            #pragma unroll
            for (int j = 0; j < 4; j++) o[i][j] *= alpha;
        }

        __syncthreads();   // done reading KP as K^T
        #pragma unroll
        for (int i = 0; i < 4; i++) {
            float4 pv = {s[i][0], s[i][1], s[i][2], s[i][3]};
            *(float4*)&KP[r4 + i][c4] = pv;
        }
        __syncthreads();

        // O += P @ V
        #pragma unroll
        for (int c0 = 0; c0 < 64; c0 += 4) {
            float preg[4][4];
            #pragma unroll
            for (int i = 0; i < 4; i++) {
                float4 t = *(const float4*)&KP[r4 + i][c0];
                preg[i][0] = t.x; preg[i][1] = t.y; preg[i][2] = t.z; preg[i][3] = t.w;
            }
            #pragma unroll
            for (int cc = 0; cc < 4; cc++) {
                float4 vt = *(const float4*)&Vs[c0 + cc][c4];
                float vr[4] = {vt.x, vt.y, vt.z, vt.w};
                #pragma unroll
                for (int i = 0; i < 4; i++)
                    #pragma unroll
                    for (int j = 0; j < 4; j++)
                        o[i][j] += preg[i][cc] * vr[j];
            }
        }
    }

    float* ybase = Yg + ((long long)b * SS + step * MM + qt * 64) * DD + h * HDIM;
    #pragma unroll
    for (int i = 0; i < 4; i++) {
        float inv = 1.f / l_i[i];
        float4 ov = {o[i][0]*inv, o[i][1]*inv, o[i][2]*inv, o[i][3]*inv};
        *(float4*)(ybase + (long long)(r4 + i) * DD + c4) = ov;
    }
}

// ---------------- host orchestration ----------------
static void launch_gemm(const float* A, const float* B, float* C,
                        int Mtot, int N, int K,
                        long long a_bs, int a_off, int Mchunk,
                        long long c_bs, int c_off, int acc)
{
    dim3 grid(N / 64, Mtot / 64);
    sgemm_kernel<<<grid, 256>>>(A, B, C, Mtot, N, K, a_bs, a_off, Mchunk, c_bs, c_off, acc);
}

extern "C" void kernel_launch(void* const* d_in, const int* in_sizes, int n_in,
                              void* d_out, int out_size)
{
    const float* x     = (const float*)d_in[0];
    const float* fcos  = (const float*)d_in[1];
    const float* fsin  = (const float*)d_in[2];
    const float* wq    = (const float*)d_in[3];
    const float* wk    = (const float*)d_in[4];
    const float* wv    = (const float*)d_in[5];
    const float* wo    = (const float*)d_in[6];
    const float* wm    = (const float*)d_in[7];
    const float* wkm   = (const float*)d_in[8];
    const float* wvm   = (const float*)d_in[9];
    const float* w1    = (const float*)d_in[10];
    const float* w3    = (const float*)d_in[11];   // note: setup_inputs order is w1, w3, w2
    const float* w2    = (const float*)d_in[12];
    const float* ffn_w = (const float*)d_in[13];
    const float* mem_w = (const float*)d_in[14];
    const float* omem  = (const float*)d_in[15];
    float* out = (float*)d_out;

    float *Y, *Qb, *Kb, *Vb, *OM2, *HN, *H1, *H3, *OMN;
    cudaGetSymbolAddress((void**)&Y,   g_Y);
    cudaGetSymbolAddress((void**)&Qb,  g_Q);
    cudaGetSymbolAddress((void**)&Kb,  g_K);
    cudaGetSymbolAddress((void**)&Vb,  g_V);
    cudaGetSymbolAddress((void**)&OM2, g_OM2);
    cudaGetSymbolAddress((void**)&HN,  g_HN);
    cudaGetSymbolAddress((void**)&H1,  g_H1);
    cudaGetSymbolAddress((void**)&H3,  g_H3);
    cudaGetSymbolAddress((void**)&OMN, g_OMN);

    const long long XBS = (long long)SS * DD;   // x batch stride
    const long long LBS = (long long)LL * DD;   // q/k/v batch stride
    const long long MBS = (long long)MM * DD;   // om-chunk batch stride

    for (int step = 0; step < NSTEP; step++) {
        // xq/xk/xv -> rows M..L of Q/K/V
        launch_gemm(x, wq, Qb, BB*MM, DD, DD, XBS, step*MM, MM, LBS, MM, 0);
        launch_gemm(x, wk, Kb, BB*MM, DD, DD, XBS, step*MM, MM, LBS, MM, 0);
        launch_gemm(x, wv, Vb, BB*MM, DD, DD, XBS, step*MM, MM, LBS, MM, 0);

        // om @ wm  (step 0: origin_mem broadcast across batch via a_bs=0)
        if (step == 0)
            launch_gemm(omem, wm, OM2, BB*MM, DD, DD, 0, 0, MM, MBS, 0, 0);
        else
            launch_gemm(Y, wm, OM2, BB*MM, DD, DD, XBS, (step-1)*MM, MM, MBS, 0, 0);

        // FFN with residual into OM2
        rmsnorm_kernel<<<BB*MM, 256>>>(OM2, ffn_w, HN);
        launch_gemm(HN, w1, H1, BB*MM, HID, DD, 0, 0, BB*MM, 0, 0, 0);
        launch_gemm(HN, w3, H3, BB*MM, HID, DD, 0, 0, BB*MM, 0, 0, 0);
        {
            int n4 = BB * MM * HID / 4;
            silu_mul_kernel<<<(n4 + 255) / 256, 256>>>(H1, H3, n4);
        }
        launch_gemm(H1, w2, OM2, BB*MM, DD, HID, 0, 0, BB*MM, 0, 0, 1);  // accumulate

        rmsnorm_kernel<<<BB*MM, 256>>>(OM2, mem_w, OMN);

        // mk -> K rows 0..M ; mv -> V rows 0..M   (mq never needed: out[:, :M] discarded)
        launch_gemm(OMN, wkm, Kb, BB*MM, DD, DD, MBS, 0, MM, LBS, 0, 0);
        launch_gemm(OMN, wvm, Vb, BB*MM, DD, DD, MBS, 0, MM, LBS, 0, 0);

        // RoPE: K rows 0..L (pos l), Q rows M..L (pos l)
        {
            int totK = BB * LL * HH * 32;
            rope_kernel<<<(totK + 255) / 256, 256>>>(Kb, fcos, fsin, 0, LL);
            int totQ = BB * MM * HH * 32;
            rope_kernel<<<(totQ + 255) / 256, 256>>>(Qb, fcos, fsin, MM, MM);
        }

        // attention (q rows M..L only) -> Y[:, step*M : (step+1)*M]
        attn_kernel<<<dim3(8, HH, BB), 256>>>(Qb, Kb, Vb, Y, step);
    }

    // final projection: out = Y @ wo
    launch_gemm(Y, wo, out, BB*SS, DD, DD, 0, 0, BB*SS, 0, 0, 0);
}